// round 1
// baseline (speedup 1.0000x reference)
#include <cuda_runtime.h>
#include <cstdint>

// Problem constants (fixed by the reference setup)
#define PB 4          // batch
#define PN 16384      // points
#define PS 2048       // query points
#define PC 64         // feature channels
#define PK 33         // 1 (fps) + 32 (ball)
#define PNS 32        // nsample
#define JTOT (PS * PK)        // 67584 = 2112 * 32
#define OUTC (6 + PC)         // 70

// Scratch (static device allocations are allowed)
__device__ int   g_idx[PB * PS * PK];                 // gathered indices incl. fps at slot 0
__device__ float4 g_featT4[(size_t)PB * PN * PC / 4]; // features transposed to (B, N, C), 16B aligned

// ---------------------------------------------------------------------------
// K1: transpose features (B, C, N) -> (B, N, C)
// ---------------------------------------------------------------------------
__global__ void __launch_bounds__(256) transpose_feat(const float* __restrict__ f) {
    __shared__ float tile[32][33];
    float* ft = reinterpret_cast<float*>(g_featT4);
    int b  = blockIdx.z;
    int n0 = blockIdx.x * 32;
    int c0 = blockIdx.y * 32;
    const float* fb  = f  + (size_t)b * PC * PN;
    float*       ftb = ft + (size_t)b * PN * PC;
#pragma unroll
    for (int i = threadIdx.y; i < 32; i += 8)
        tile[i][threadIdx.x] = fb[(size_t)(c0 + i) * PN + n0 + threadIdx.x];
    __syncthreads();
#pragma unroll
    for (int i = threadIdx.y; i < 32; i += 8)
        ftb[(size_t)(n0 + i) * PC + c0 + threadIdx.x] = tile[threadIdx.x][i];
}

// ---------------------------------------------------------------------------
// K2: ball query — one warp per query point. Ascending-index scan with early
// exit; ballot + prefix popc emits the first 32 in-radius indices in order.
// ---------------------------------------------------------------------------
__global__ void __launch_bounds__(256) ball_query(const float* __restrict__ xyz,
                                                  const float* __restrict__ new_xyz,
                                                  const int*   __restrict__ fps) {
    int gwarp = (blockIdx.x * blockDim.x + threadIdx.x) >> 5;
    int lane  = threadIdx.x & 31;
    if (gwarp >= PB * PS) return;
    int b = gwarp / PS;
    int s = gwarp - b * PS;

    const float* q = new_xyz + ((size_t)b * PS + s) * 3;
    float qx = q[0], qy = q[1], qz = q[2];
    const float* xb = xyz + (size_t)b * PN * 3;
    int* out = g_idx + (size_t)gwarp * PK;

    if (lane == 0) out[0] = fps[b * PS + s];

    // Threshold: JAX computes radius*radius in f64 (0.010000000000000002)
    // and casts to f32 for the comparison -> exactly (float)0.01.
    const float R2 = 0.01f;

    int cnt = 0;
    int first = 0;
    const unsigned FULL = 0xffffffffu;

    for (int n0 = 0; n0 < PN && cnt < PNS; n0 += 32) {
        int n = n0 + lane;
        const float* p = xb + 3 * n;
        // Non-fused, (dx^2 + dy^2) + dz^2 order — match XLA's unfused lowering.
        float dx = __fsub_rn(qx, p[0]);
        float dy = __fsub_rn(qy, p[1]);
        float dz = __fsub_rn(qz, p[2]);
        float d2 = __fadd_rn(__fadd_rn(__fmul_rn(dx, dx), __fmul_rn(dy, dy)),
                             __fmul_rn(dz, dz));
        bool hit = d2 < R2;
        unsigned m = __ballot_sync(FULL, hit);
        if (m) {
            if (cnt == 0) first = n0 + __ffs(m) - 1;  // uniform across warp
            if (hit) {
                int pos = cnt + __popc(m & ((1u << lane) - 1u));
                if (pos < PNS) out[pos + 1] = n;
            }
            cnt += __popc(m);
        }
    }
    int fill = (cnt == 0) ? 0 : first;   // cand==N -> first (or 0 if none)
    if (cnt > PNS) cnt = PNS;
    if (lane >= cnt) out[lane + 1] = fill;
}

// ---------------------------------------------------------------------------
// K3: gather + write. Block = 256 threads, handles 32 consecutive j = s*33+k
// for one batch. Coalesced 256B row reads from g_featT, smem transpose,
// coalesced 128B writes per (channel, j-tile).
// ---------------------------------------------------------------------------
__global__ void __launch_bounds__(256) gather_write(const float* __restrict__ xyz,
                                                    const float* __restrict__ new_xyz,
                                                    float* __restrict__ out) {
    __shared__ float tile[32][PC + 1];   // +1 pad: conflict-free transpose read
    __shared__ int   sn[32];
    __shared__ float sxyz[32][3];
    __shared__ float sctr[32][3];

    int b   = blockIdx.y;
    int j0  = blockIdx.x * 32;
    int tid = threadIdx.x;

    if (tid < 32) {
        int j = j0 + tid;
        int n = g_idx[(size_t)b * JTOT + j];
        sn[tid] = n;
        int s = j / PK;
        const float* p = xyz     + ((size_t)b * PN + n) * 3;
        const float* q = new_xyz + ((size_t)b * PS + s) * 3;
        float x = p[0], y = p[1], z = p[2];
        sxyz[tid][0] = x;           sxyz[tid][1] = y;           sxyz[tid][2] = z;
        sctr[tid][0] = x - q[0];    sctr[tid][1] = y - q[1];    sctr[tid][2] = z - q[2];
    }
    __syncthreads();

    // Load 32 feature rows (64 floats = 16 float4 each): 512 float4 / 256 thr
    const float4* ftb = g_featT4 + (size_t)b * PN * (PC / 4);
#pragma unroll
    for (int it = 0; it < 2; it++) {
        int lin = tid + it * 256;
        int jj  = lin >> 4;
        int qd  = lin & 15;
        float4 v = ftb[(size_t)sn[jj] * (PC / 4) + qd];
        tile[jj][qd * 4 + 0] = v.x;
        tile[jj][qd * 4 + 1] = v.y;
        tile[jj][qd * 4 + 2] = v.z;
        tile[jj][qd * 4 + 3] = v.w;
    }
    __syncthreads();

    float* ob = out + (size_t)b * OUTC * JTOT;

    // Channels 0..5: raw xyz then centered xyz (192 threads)
    if (tid < 192) {
        int c  = tid >> 5;
        int jj = tid & 31;
        float v = (c < 3) ? sxyz[jj][c] : sctr[jj][c - 3];
        ob[(size_t)c * JTOT + j0 + jj] = v;
    }

    // Channels 6..69: features. 64 x 32 writes, 8 per thread.
#pragma unroll
    for (int it = 0; it < 8; it++) {
        int c  = (tid >> 5) + it * 8;
        int jj = tid & 31;
        ob[(size_t)(6 + c) * JTOT + j0 + jj] = tile[jj][c];
    }
}

// ---------------------------------------------------------------------------
extern "C" void kernel_launch(void* const* d_in, const int* in_sizes, int n_in,
                              void* d_out, int out_size) {
    const float* xyz      = (const float*)d_in[0];   // (4,16384,3)
    const float* new_xyz  = (const float*)d_in[1];   // (4,2048,3)
    const float* features = (const float*)d_in[2];   // (4,64,16384)
    const int*   fps_idx  = (const int*)  d_in[3];   // (4,2048)
    float* out = (float*)d_out;                      // (4,70,2048,33)

    // K1: transpose features -> (B, N, C)
    {
        dim3 grid(PN / 32, PC / 32, PB);
        dim3 blk(32, 8);
        transpose_feat<<<grid, blk>>>(features);
    }
    // K2: ball query (one warp per query, 8192 warps)
    {
        int threads = 256;
        int blocks  = (PB * PS * 32) / threads;  // 1024
        ball_query<<<blocks, threads>>>(xyz, new_xyz, fps_idx);
    }
    // K3: gather + write output
    {
        dim3 grid(JTOT / 32, PB);   // (2112, 4)
        gather_write<<<grid, 256>>>(xyz, new_xyz, out);
    }
}

// round 2
// speedup vs baseline: 3.6676x; 3.6676x over previous
#include <cuda_runtime.h>
#include <cstdint>

// Problem constants (fixed by the reference setup)
#define PB 4          // batch
#define PN 16384      // points
#define PS 2048       // query points
#define PC 64         // feature channels
#define PK 33         // 1 (fps) + 32 (ball)
#define PNS 32        // nsample
#define JTOT (PS * PK)        // 67584 = 2112 * 32
#define OUTC (6 + PC)         // 70
#define GR 10                 // grid cells per dim (cell size = radius = 0.1)
#define NC (GR * GR * GR)     // 1000 cells

// Scratch (static device allocations are allowed)
__device__ int    g_idx[PB * PS * PK];
__device__ float4 g_featT4[(size_t)PB * PN * PC / 4];
__device__ int    g_cellCnt[PB * NC];
__device__ int    g_cellStart[PB * (NC + 1)];
__device__ int    g_cellCursor[PB * NC];
__device__ float4 g_pts[PB * PN];      // grid-reordered {x, y, z, bitcast(idx)}

__device__ __forceinline__ int cell_of(float x, float y, float z) {
    int ix = min((int)(x * 10.0f), GR - 1);
    int iy = min((int)(y * 10.0f), GR - 1);
    int iz = min((int)(z * 10.0f), GR - 1);
    return (iz * GR + iy) * GR + ix;
}

// ---------------------------------------------------------------------------
// Grid build
// ---------------------------------------------------------------------------
__global__ void zero_counts() {
    int i = blockIdx.x * blockDim.x + threadIdx.x;
    if (i < PB * NC) g_cellCnt[i] = 0;
}

__global__ void count_cells(const float* __restrict__ xyz) {
    int i = blockIdx.x * blockDim.x + threadIdx.x;
    if (i >= PB * PN) return;
    const float* p = xyz + 3 * (size_t)i;
    int b = i >> 14;  // / PN
    atomicAdd(&g_cellCnt[b * NC + cell_of(p[0], p[1], p[2])], 1);
}

__global__ void __launch_bounds__(1024) scan_cells() {
    __shared__ int s[1024];
    int b = blockIdx.x;
    int t = threadIdx.x;
    int cnt = (t < NC) ? g_cellCnt[b * NC + t] : 0;
    s[t] = cnt;
    __syncthreads();
#pragma unroll
    for (int off = 1; off < 1024; off <<= 1) {
        int tmp = 0;
        if (t >= off) tmp = s[t - off];
        __syncthreads();
        if (t >= off) s[t] += tmp;
        __syncthreads();
    }
    if (t < NC) {
        int excl = s[t] - cnt;
        g_cellStart[b * (NC + 1) + t]  = excl;
        g_cellCursor[b * NC + t]       = excl;
        if (t == NC - 1) g_cellStart[b * (NC + 1) + NC] = s[t];
    }
}

__global__ void scatter_pts(const float* __restrict__ xyz) {
    int i = blockIdx.x * blockDim.x + threadIdx.x;
    if (i >= PB * PN) return;
    const float* p = xyz + 3 * (size_t)i;
    float x = p[0], y = p[1], z = p[2];
    int b = i >> 14;
    int n = i & (PN - 1);
    int pos = atomicAdd(&g_cellCursor[b * NC + cell_of(x, y, z)], 1);
    g_pts[b * PN + pos] = make_float4(x, y, z, __int_as_float(n));
}

// ---------------------------------------------------------------------------
// K2: ball query via grid — one warp per query. Collect all in-radius hits
// from the 27-cell neighborhood (9 contiguous segments), then select the 32
// smallest indices by rank-counting. Output order-independent of scatter.
// ---------------------------------------------------------------------------
#define CAP 256

__global__ void __launch_bounds__(256) ball_query_grid(const float* __restrict__ new_xyz,
                                                       const int*   __restrict__ fps) {
    __shared__ int buf[8][264];   // 264*4 = 1056B: keeps each warp's buf 16B-aligned
    int wi   = threadIdx.x >> 5;
    int lane = threadIdx.x & 31;
    int gw   = blockIdx.x * 8 + wi;
    int b = gw >> 11;             // / PS
    int s = gw & (PS - 1);

    const float* q = new_xyz + ((size_t)b * PS + s) * 3;
    float qx = q[0], qy = q[1], qz = q[2];
    int* out = g_idx + (size_t)gw * PK;
    if (lane == 0) out[0] = fps[b * PS + s];

    int cx = min((int)(qx * 10.0f), GR - 1);
    int cy = min((int)(qy * 10.0f), GR - 1);
    int cz = min((int)(qz * 10.0f), GR - 1);

    const float4* pts  = g_pts + (size_t)b * PN;
    const int*    cst  = g_cellStart + (size_t)b * (NC + 1);
    int* wbuf = buf[wi];

    const float R2 = 0.01f;       // (float)(0.1*0.1 in f64) == 0.01f
    const unsigned FULL = 0xffffffffu;
    int cnt = 0;

    int z0 = max(cz - 1, 0), z1 = min(cz + 1, GR - 1);
    int y0 = max(cy - 1, 0), y1 = min(cy + 1, GR - 1);
    int x0 = max(cx - 1, 0), x1 = min(cx + 1, GR - 1);

    for (int zz = z0; zz <= z1; zz++) {
        for (int yy = y0; yy <= y1; yy++) {
            int cbase = (zz * GR + yy) * GR;
            int beg = cst[cbase + x0];
            int end = cst[cbase + x1 + 1];
            for (; beg < end; beg += 32) {
                int i = beg + lane;
                bool hit = false;
                int pid = 0;
                if (i < end) {
                    float4 v = pts[i];
                    float dx = __fsub_rn(qx, v.x);
                    float dy = __fsub_rn(qy, v.y);
                    float dz = __fsub_rn(qz, v.z);
                    float d2 = __fadd_rn(__fadd_rn(__fmul_rn(dx, dx), __fmul_rn(dy, dy)),
                                         __fmul_rn(dz, dz));
                    hit = d2 < R2;
                    pid = __float_as_int(v.w);
                }
                unsigned m = __ballot_sync(FULL, hit);
                if (hit) {
                    int pos = cnt + __popc(m & ((1u << lane) - 1u));
                    if (pos < CAP) wbuf[pos] = pid;
                }
                cnt += __popc(m);
            }
        }
    }

    int M = min(cnt, CAP);
    int Mp = (M + 3) & ~3;
    if (lane < Mp - M) wbuf[M + lane] = 0x7fffffff;   // pad for int4 reads
    __syncwarp();

    // Rank-by-counting selection: 32 smallest hit indices, ascending.
    int minhit = 0x7fffffff;
    const int4* b4 = (const int4*)wbuf;
    for (int i = lane; i < M; i += 32) {
        int h = wbuf[i];
        minhit = min(minhit, h);
        int rank = 0;
        int nq = Mp >> 2;
        for (int j = 0; j < nq; j++) {
            int4 w = b4[j];
            rank += (w.x < h) + (w.y < h) + (w.z < h) + (w.w < h);
        }
        if (rank < PNS) out[1 + rank] = h;
    }
#pragma unroll
    for (int off = 16; off; off >>= 1)
        minhit = min(minhit, __shfl_xor_sync(FULL, minhit, off));
    int fill = (cnt == 0) ? 0 : minhit;
    int c = min(cnt, PNS);
    if (lane >= c) out[1 + lane] = fill;
}

// ---------------------------------------------------------------------------
// K1: transpose features (B, C, N) -> (B, N, C)
// ---------------------------------------------------------------------------
__global__ void __launch_bounds__(256) transpose_feat(const float* __restrict__ f) {
    __shared__ float tile[32][33];
    float* ft = reinterpret_cast<float*>(g_featT4);
    int b  = blockIdx.z;
    int n0 = blockIdx.x * 32;
    int c0 = blockIdx.y * 32;
    const float* fb  = f  + (size_t)b * PC * PN;
    float*       ftb = ft + (size_t)b * PN * PC;
#pragma unroll
    for (int i = threadIdx.y; i < 32; i += 8)
        tile[i][threadIdx.x] = fb[(size_t)(c0 + i) * PN + n0 + threadIdx.x];
    __syncthreads();
#pragma unroll
    for (int i = threadIdx.y; i < 32; i += 8)
        ftb[(size_t)(n0 + i) * PC + c0 + threadIdx.x] = tile[threadIdx.x][i];
}

// ---------------------------------------------------------------------------
// K3: gather + write
// ---------------------------------------------------------------------------
__global__ void __launch_bounds__(256) gather_write(const float* __restrict__ xyz,
                                                    const float* __restrict__ new_xyz,
                                                    float* __restrict__ out) {
    __shared__ float tile[32][PC + 1];
    __shared__ int   sn[32];
    __shared__ float sxyz[32][3];
    __shared__ float sctr[32][3];

    int b   = blockIdx.y;
    int j0  = blockIdx.x * 32;
    int tid = threadIdx.x;

    if (tid < 32) {
        int j = j0 + tid;
        int n = g_idx[(size_t)b * JTOT + j];
        sn[tid] = n;
        int s = j / PK;
        const float* p = xyz     + ((size_t)b * PN + n) * 3;
        const float* q = new_xyz + ((size_t)b * PS + s) * 3;
        float x = p[0], y = p[1], z = p[2];
        sxyz[tid][0] = x;           sxyz[tid][1] = y;           sxyz[tid][2] = z;
        sctr[tid][0] = x - q[0];    sctr[tid][1] = y - q[1];    sctr[tid][2] = z - q[2];
    }
    __syncthreads();

    const float4* ftb = g_featT4 + (size_t)b * PN * (PC / 4);
#pragma unroll
    for (int it = 0; it < 2; it++) {
        int lin = tid + it * 256;
        int jj  = lin >> 4;
        int qd  = lin & 15;
        float4 v = ftb[(size_t)sn[jj] * (PC / 4) + qd];
        tile[jj][qd * 4 + 0] = v.x;
        tile[jj][qd * 4 + 1] = v.y;
        tile[jj][qd * 4 + 2] = v.z;
        tile[jj][qd * 4 + 3] = v.w;
    }
    __syncthreads();

    float* ob = out + (size_t)b * OUTC * JTOT;
    if (tid < 192) {
        int c  = tid >> 5;
        int jj = tid & 31;
        float v = (c < 3) ? sxyz[jj][c] : sctr[jj][c - 3];
        ob[(size_t)c * JTOT + j0 + jj] = v;
    }
#pragma unroll
    for (int it = 0; it < 8; it++) {
        int c  = (tid >> 5) + it * 8;
        int jj = tid & 31;
        ob[(size_t)(6 + c) * JTOT + j0 + jj] = tile[jj][c];
    }
}

// ---------------------------------------------------------------------------
extern "C" void kernel_launch(void* const* d_in, const int* in_sizes, int n_in,
                              void* d_out, int out_size) {
    const float* xyz      = (const float*)d_in[0];   // (4,16384,3)
    const float* new_xyz  = (const float*)d_in[1];   // (4,2048,3)
    const float* features = (const float*)d_in[2];   // (4,64,16384)
    const int*   fps_idx  = (const int*)  d_in[3];   // (4,2048)
    float* out = (float*)d_out;                      // (4,70,2048,33)

    // Grid build
    zero_counts<<<(PB * NC + 255) / 256, 256>>>();
    count_cells<<<(PB * PN + 255) / 256, 256>>>(xyz);
    scan_cells<<<PB, 1024>>>();
    scatter_pts<<<(PB * PN + 255) / 256, 256>>>(xyz);

    // Transpose features (independent of grid)
    {
        dim3 grid(PN / 32, PC / 32, PB);
        dim3 blk(32, 8);
        transpose_feat<<<grid, blk>>>(features);
    }

    // Ball query via grid: one warp per query
    ball_query_grid<<<PB * PS / 8, 256>>>(new_xyz, fps_idx);

    // Gather + write output
    {
        dim3 grid(JTOT / 32, PB);
        gather_write<<<grid, 256>>>(xyz, new_xyz, out);
    }
}